// round 16
// baseline (speedup 1.0000x reference)
#include <cuda_runtime.h>
#include <cstdint>

// ============================================================================
// GENERICLayer (B=8192, D=64, H=128) via warp-level mma.sync (HMMA, bf16).
//   out = [z_q, -z_p] (exact fp32) + (z Wf^T)^2 * ((W2*silu'(z W1^T+b1)) @ W1)
// Exact collapse of the reference:
//   * eigh(diag(a^2)) reconstructs it exactly -> irr_d = a_d^2 * gS_d
//   * reversible = concat(z[:,32:], -z[:,:32])
//
// R15: weight fragment packing hoisted into a tiny prep kernel writing
// __device__ globals (40KB, L2-resident, shared by all CTAs).  Main kernel
// has NO smem staging and NO pre-compute __syncthreads: Z A-frags are built
// directly from global, B-frags are LDG'd from the prepacked tables inside
// the MMA loops (L1-hot across warps).  Warp-pair n/h-split as in R14:
//   phase 1: 48 MMAs/warp (half of U + half of A, K=64)
//   silu' in-register; own U half == own phase-2 k-tiles (k = h)
//   phase 2: 32 MMAs/warp partial gS; 16KB smem exchange; epilogue.
// ============================================================================

#define NBLK 128
#define THREADS 256

__device__ uint2 gBU[2048];   // [(kt*128 + h)*4 + q]  : B frags of W1^T (U GEMM)
__device__ uint2 gBF[1024];   // [(kt*64  + d)*4 + q]  : B frags of Wf^T (A GEMM)
__device__ uint2 gBG[2048];   // [(kt*64  + d)*4 + q]  : B frags of W1   (gS GEMM)

__device__ __forceinline__ unsigned packbf(float lo, float hi) {
    unsigned r;
    asm("cvt.rn.bf16x2.f32 %0, %1, %2;" : "=r"(r) : "f"(hi), "f"(lo));
    return r;
}
__device__ __forceinline__ void mma16816(float d[4], const unsigned a[4],
                                         unsigned b0, unsigned b1) {
    asm volatile(
        "mma.sync.aligned.m16n8k16.row.col.f32.bf16.bf16.f32 "
        "{%0,%1,%2,%3}, {%4,%5,%6,%7}, {%8,%9}, {%0,%1,%2,%3};"
        : "+f"(d[0]), "+f"(d[1]), "+f"(d[2]), "+f"(d[3])
        : "r"(a[0]), "r"(a[1]), "r"(a[2]), "r"(a[3]), "r"(b0), "r"(b1));
}

// ---- prep: pack weight fragments once (8 CTAs x 256 thr = 2048 threads) ----
__global__ void __launch_bounds__(256, 1)
prep_pack(const float* __restrict__ W1, const float* __restrict__ Wf)
{
    const int i = blockIdx.x * 256 + threadIdx.x;   // 0..2047
    // BU[(kt*128+h)*4+q] = pairs of W1 row h, cols kt*16 + {2q,2q+1,2q+8,2q+9}
    {
        int h = (i >> 2) & 127, q = i & 3;
        int c = (i >> 9) * 16 + 2 * q;
        gBU[i] = make_uint2(packbf(W1[h * 64 + c],     W1[h * 64 + c + 1]),
                            packbf(W1[h * 64 + c + 8], W1[h * 64 + c + 9]));
    }
    // BF[(kt*64+d)*4+q] = pairs of Wf row d, cols kt*16 + {...}
    if (i < 1024) {
        int d = (i >> 2) & 63, q = i & 3;
        int c = (i >> 8) * 16 + 2 * q;
        gBF[i] = make_uint2(packbf(Wf[d * 64 + c],     Wf[d * 64 + c + 1]),
                            packbf(Wf[d * 64 + c + 8], Wf[d * 64 + c + 9]));
    }
    // BG[(kt*64+d)*4+q] = pairs of W1 col d, rows kt*16 + {2q,2q+1,2q+8,2q+9}
    {
        int d = (i >> 2) & 63, q = i & 3;
        int rr = (i >> 8) * 16 + 2 * q;
        gBG[i] = make_uint2(packbf(W1[rr * 64 + d],       W1[(rr + 1) * 64 + d]),
                            packbf(W1[(rr + 8) * 64 + d], W1[(rr + 9) * 64 + d]));
    }
}

// ---- main kernel -----------------------------------------------------------
__global__ void __launch_bounds__(THREADS, 1)
generic_layer_hmma(const float* __restrict__ z,
                   const float* __restrict__ b1,
                   const float* __restrict__ W2,
                   float* __restrict__ out)
{
    __shared__ float4 XG[4 * 2 * 4 * 32];   // [ws][dest_half][n4][lane], 16KB

    const int tid  = threadIdx.x;
    const int wid  = tid >> 5, l = tid & 31;
    const int half = wid >> 2;            // n/h-split half (0 or 1)
    const int oh   = 1 - half;
    const int ws   = wid & 3;             // row-slab id
    const int lq   = l >> 2, lr = l & 3;
    const int row_base = blockIdx.x * 64;
    const int r0   = ws * 16 + lq;        // lane's base row in the 64-row tile

    // ---- A-fragments of Z straight from global (16 LDG.64 + pack) ---------
    const float* zr0p = z + (row_base + r0) * 64;
    const float* zr1p = z + (row_base + r0 + 8) * 64;
    float2 zl[4][4];
    #pragma unroll
    for (int kt = 0; kt < 4; kt++) {
        int c = kt * 16 + 2 * lr;
        zl[kt][0] = *reinterpret_cast<const float2*>(zr0p + c);
        zl[kt][1] = *reinterpret_cast<const float2*>(zr1p + c);
        zl[kt][2] = *reinterpret_cast<const float2*>(zr0p + c + 8);
        zl[kt][3] = *reinterpret_cast<const float2*>(zr1p + c + 8);
    }
    unsigned afr[4][4];
    #pragma unroll
    for (int kt = 0; kt < 4; kt++)
        #pragma unroll
        for (int j = 0; j < 4; j++)
            afr[kt][j] = packbf(zl[kt][j].x, zl[kt][j].y);

    // preload bias/W2 pairs for own 8 h-groups (L1-hot, 512B tables)
    float2 bb[8], ww[8];
    #pragma unroll
    for (int n8 = 0; n8 < 8; n8++) {
        int c0 = (half * 8 + n8) * 8 + lr * 2;
        bb[n8] = *reinterpret_cast<const float2*>(b1 + c0);
        ww[n8] = *reinterpret_cast<const float2*>(W2 + c0);
    }

    // ---- phase 1: U (own 8 n-tiles) + A (own 4 n-tiles), K=64 -------------
    float uacc[8][4], facc[4][4];
    #pragma unroll
    for (int n = 0; n < 8; n++)
        #pragma unroll
        for (int j = 0; j < 4; j++) uacc[n][j] = 0.f;
    #pragma unroll
    for (int n = 0; n < 4; n++)
        #pragma unroll
        for (int j = 0; j < 4; j++) facc[n][j] = 0.f;

    #pragma unroll
    for (int kt = 0; kt < 4; kt++) {
        uint2 bu[8], bf4[4];
        #pragma unroll
        for (int n8 = 0; n8 < 8; n8++)
            bu[n8] = gBU[(kt * 128 + (half * 8 + n8) * 8 + lq) * 4 + lr];
        #pragma unroll
        for (int n4 = 0; n4 < 4; n4++)
            bf4[n4] = gBF[(kt * 64 + (half * 4 + n4) * 8 + lq) * 4 + lr];
        #pragma unroll
        for (int n8 = 0; n8 < 8; n8++)
            mma16816(uacc[n8], afr[kt], bu[n8].x, bu[n8].y);
        #pragma unroll
        for (int n4 = 0; n4 < 4; n4++)
            mma16816(facc[n4], afr[kt], bf4[n4].x, bf4[n4].y);
    }

    // ---- silu' in-register; C-frag pairs become A-frags for gS GEMM -------
    unsigned gfr[4][4];
    #pragma unroll
    for (int n8 = 0; n8 < 8; n8++) {
        float g[4];
        #pragma unroll
        for (int j = 0; j < 4; j++) {
            float u = uacc[n8][j] + ((j & 1) ? bb[n8].y : bb[n8].x);
            float e = __expf(-u);
            float s = __fdividef(1.0f, 1.0f + e);
            g[j] = ((j & 1) ? ww[n8].y : ww[n8].x) * s * fmaf(u, 1.0f - s, 1.0f);
        }
        int jkt = n8 >> 1, hi = n8 & 1;
        gfr[jkt][hi * 2 + 0] = packbf(g[0], g[1]);   // rows r0
        gfr[jkt][hi * 2 + 1] = packbf(g[2], g[3]);   // rows r0+8
    }

    // ---- phase 2: partial gS over own 4 h k-tiles, all 8 n-tiles ----------
    float gsacc[8][4];
    #pragma unroll
    for (int n = 0; n < 8; n++)
        #pragma unroll
        for (int j = 0; j < 4; j++) gsacc[n][j] = 0.f;

    #pragma unroll
    for (int jkt = 0; jkt < 4; jkt++) {
        int ktg = half * 4 + jkt;
        uint2 bg[8];
        #pragma unroll
        for (int n = 0; n < 8; n++)
            bg[n] = gBG[(ktg * 64 + n * 8 + lq) * 4 + lr];
        #pragma unroll
        for (int n = 0; n < 8; n++)
            mma16816(gsacc[n], gfr[jkt], bg[n].x, bg[n].y);
    }

    // ---- exchange: ship partials for the partner's 4 output n-tiles -------
    #pragma unroll
    for (int n4 = 0; n4 < 4; n4++) {
        const float* gp = gsacc[oh * 4 + n4];
        XG[((ws * 2 + oh) * 4 + n4) * 32 + l] =
            make_float4(gp[0], gp[1], gp[2], gp[3]);
    }
    __syncthreads();

    // ---- epilogue: finalize own 4 n-tiles (own 32 output cols) ------------
    #pragma unroll
    for (int n4 = 0; n4 < 4; n4++) {
        int ng = half * 4 + n4;
        float4 px = XG[((ws * 2 + half) * 4 + n4) * 32 + l];
        float gs0 = gsacc[ng][0] + px.x;
        float gs1 = gsacc[ng][1] + px.y;
        float gs2 = gsacc[ng][2] + px.z;
        float gs3 = gsacc[ng][3] + px.w;

        int c0 = ng * 8 + lr * 2;
        int zc = c0 ^ 32;                       // rev source column (pair-safe)
        float sgn = (c0 < 32) ? 1.0f : -1.0f;
        float2 zv0 = *reinterpret_cast<const float2*>(zr0p + zc);   // L1 hit
        float2 zv1 = *reinterpret_cast<const float2*>(zr1p + zc);
        float a0 = facc[n4][0], a1 = facc[n4][1], a2 = facc[n4][2], a3 = facc[n4][3];
        float2 o0, o1;
        o0.x = fmaf(a0 * a0, gs0, sgn * zv0.x);
        o0.y = fmaf(a1 * a1, gs1, sgn * zv0.y);
        o1.x = fmaf(a2 * a2, gs2, sgn * zv1.x);
        o1.y = fmaf(a3 * a3, gs3, sgn * zv1.y);
        *reinterpret_cast<float2*>(out + (row_base + r0) * 64 + c0)     = o0;
        *reinterpret_cast<float2*>(out + (row_base + r0 + 8) * 64 + c0) = o1;
    }
}

extern "C" void kernel_launch(void* const* d_in, const int* in_sizes, int n_in,
                              void* d_out, int out_size) {
    const float* z  = (const float*)d_in[0];
    const float* W1 = (const float*)d_in[1];
    const float* b1 = (const float*)d_in[2];
    const float* W2 = (const float*)d_in[3];
    // d_in[4] = b2 : drops out of the gradient
    const float* Wf = (const float*)d_in[5];
    float* out = (float*)d_out;

    prep_pack<<<8, 256>>>(W1, Wf);
    generic_layer_hmma<<<NBLK, THREADS>>>(z, b1, W2, out);
}